// round 5
// baseline (speedup 1.0000x reference)
#include <cuda_runtime.h>
#include <cstdint>
#include <math.h>

// ---------------- problem constants ----------------
#define NTOK    32768
#define NEXP    16
#define LINP    1792
#define TPB     128
#define TOKBLK  32
#define NBLK    (NTOK / TOKBLK)   // 1024
#define NSTG    112               // 16-feature stages
#define CHW     28                // stages per warp (K-split by 4)

#define IDX_OFF (NTOK * NEXP)
#define G1_OFF  (IDX_OFF + NTOK * 2)

__device__ __align__(16) float2 g_wpack[LINP * NEXP];
__device__ float2 g_bias[NEXP];

// ---------------- helpers ----------------
__device__ __forceinline__ void fma2(unsigned long long& acc,
                                     unsigned long long x,
                                     unsigned long long w) {
    asm("fma.rn.f32x2 %0, %1, %2, %0;" : "+l"(acc) : "l"(x), "l"(w));
}
__device__ __forceinline__ unsigned long long pack2(float v) {
    unsigned long long r;
    asm("mov.b64 %0, {%1, %1};" : "=l"(r) : "f"(v));
    return r;
}
__device__ __forceinline__ float2 unpack2(unsigned long long a) {
    float2 r;
    asm("mov.b64 {%0, %1}, %2;" : "=f"(r.x), "=f"(r.y) : "l"(a));
    return r;
}
__device__ __forceinline__ float softplus_f(float x) {
    return fmaxf(x, 0.f) + log1pf(expf(-fabsf(x)));
}

// ---------------- prep ----------------
__global__ void prep_kernel(const float* __restrict__ w_route,
                            const float* __restrict__ b_route,
                            const float* __restrict__ w_noise,
                            const float* __restrict__ b_noise,
                            const float* __restrict__ city_emb,
                            const int*   __restrict__ city_index)
{
    int idx = blockIdx.x * blockDim.x + threadIdx.x;
    if (idx < LINP * NEXP) {
        int pf = idx >> 4, e = idx & 15;
        int g = pf + (pf >= 1024 ? 32 : 0);
        g_wpack[idx] = make_float2(w_route[g * 16 + e], w_noise[g * 16 + e]);
    }
    if (idx < NEXP) {
        int ci = city_index[0];
        float br = b_route[idx], bn = b_noise[idx];
        #pragma unroll
        for (int j = 0; j < 32; j++) {
            float cv = city_emb[ci * 32 + j];
            br = fmaf(cv, w_route[(1024 + j) * 16 + idx], br);
            bn = fmaf(cv, w_noise[(1024 + j) * 16 + idx], bn);
        }
        g_bias[idx] = make_float2(br, bn);
    }
}

// ---------------- main kernel ----------------
__global__ __launch_bounds__(TPB, 6)
void router_main(const float* __restrict__ mh,
                 const float* __restrict__ dt,
                 const float* __restrict__ dd,
                 const float* __restrict__ drg,
                 const float* __restrict__ dent,
                 const float* __restrict__ eps,
                 float* __restrict__ out,
                 int out_size)
{
    // main: per-warp private X tile, 16 feats x 32 tokens (512 f), 4 warps = 2048 f
    // epilogue overlay: red[3][32][17] float2 = 3264 f
    __shared__ __align__(16) float sm[3264];

    const int tid  = threadIdx.x;
    const int lane = tid & 31;
    const int w    = tid >> 5;        // K-quarter
    const int og   = lane >> 3;       // 0..3 : pairs og*4..og*4+3
    const int tg   = lane & 7;        // tokens 4*tg..4*tg+3
    const int tb   = blockIdx.x * TOKBLK;

    float* Xw = sm + w * 512;         // [16][32] transposed, XOR swizzled

    unsigned long long acc[4][4];
    #pragma unroll
    for (int j = 0; j < 4; j++) {
        unsigned long long b = (w == 0)
            ? *reinterpret_cast<const unsigned long long*>(&g_bias[og * 4 + j])
            : 0ull;
        #pragma unroll
        for (int i = 0; i < 4; i++) acc[i][j] = b;
    }

    // loader lanes: lf = feature-f4 col (0..3), lt = token low (0..7), 4 rounds
    const int lf = lane & 3;
    const int lt = lane >> 2;

    float4 xr[4];

    auto prefetch = [&](int s) {
        const float* src; int col, stride;
        if (s < 64)       { src = mh;   col = s * 16;         stride = 1024; }
        else if (s < 80)  { src = dt;   col = (s - 64) * 16;  stride = 256;  }
        else if (s < 96)  { src = dd;   col = (s - 80) * 16;  stride = 256;  }
        else if (s < 104) { src = drg;  col = (s - 96) * 16;  stride = 128;  }
        else              { src = dent; col = (s - 104) * 16; stride = 128;  }
        const float* g = src + (size_t)(tb + lt) * stride + col + 4 * lf;
        #pragma unroll
        for (int q = 0; q < 4; q++)
            xr[q] = *reinterpret_cast<const float4*>(g + (size_t)(8 * q) * stride);
    };
    auto storeX = [&]() {
        #pragma unroll
        for (int q = 0; q < 4; q++) {
            const int t = lt + 8 * q;
            const float* v = reinterpret_cast<const float*>(&xr[q]);
            #pragma unroll
            for (int j = 0; j < 4; j++) {
                const int f = 4 * lf + j;
                Xw[f * 32 + (t ^ (4 * (f & 7)))] = v[j];
            }
        }
    };

    int s = w;                         // this warp's stages: w, w+4, w+8, ...
    prefetch(s);

    for (int c = 0; c < CHW; c++) {
        storeX();
        const int scur = s;
        s += 4;
        if (c + 1 < CHW) prefetch(s);  // LDG spans compute below
        __syncwarp();                  // STS visible to whole warp

        const float2* wrow = g_wpack + (size_t)scur * 16 * NEXP + og * 4;
        #pragma unroll
        for (int f = 0; f < 16; f++) {
            const float4 xv = *reinterpret_cast<const float4*>(
                &Xw[f * 32 + ((4 * tg) ^ (4 * (f & 7)))]);
            const ulonglong2 wA =
                *reinterpret_cast<const ulonglong2*>(wrow + f * 16);
            const ulonglong2 wB =
                *reinterpret_cast<const ulonglong2*>(wrow + f * 16 + 2);
            unsigned long long xx;
            xx = pack2(xv.x);
            fma2(acc[0][0], xx, wA.x); fma2(acc[0][1], xx, wA.y);
            fma2(acc[0][2], xx, wB.x); fma2(acc[0][3], xx, wB.y);
            xx = pack2(xv.y);
            fma2(acc[1][0], xx, wA.x); fma2(acc[1][1], xx, wA.y);
            fma2(acc[1][2], xx, wB.x); fma2(acc[1][3], xx, wB.y);
            xx = pack2(xv.z);
            fma2(acc[2][0], xx, wA.x); fma2(acc[2][1], xx, wA.y);
            fma2(acc[2][2], xx, wB.x); fma2(acc[2][3], xx, wB.y);
            xx = pack2(xv.w);
            fma2(acc[3][0], xx, wA.x); fma2(acc[3][1], xx, wA.y);
            fma2(acc[3][2], xx, wB.x); fma2(acc[3][3], xx, wB.y);
        }
        __syncwarp();                  // all lanes done reading Xw before overwrite
    }

    // ---------------- K-split reduction (3 block syncs total) ----------------
    __syncthreads();
    float2* red = reinterpret_cast<float2*>(sm);
    if (w > 0) {
        float2* r = red + (w - 1) * (32 * 17);
        #pragma unroll
        for (int i = 0; i < 4; i++)
            #pragma unroll
            for (int j = 0; j < 4; j++)
                r[(4 * tg + i) * 17 + og * 4 + j] = unpack2(acc[i][j]);
    }
    __syncthreads();
    if (w == 0) {
        #pragma unroll
        for (int i = 0; i < 4; i++)
            #pragma unroll
            for (int j = 0; j < 4; j++) {
                float2 a = unpack2(acc[i][j]);
                #pragma unroll
                for (int p = 0; p < 3; p++) {
                    float2 r = red[p * (32 * 17) + (4 * tg + i) * 17 + og * 4 + j];
                    a.x += r.x; a.y += r.y;
                }
                acc[i][j] = *reinterpret_cast<unsigned long long*>(&a);
            }
        // publish final logits for epilogue threads
        #pragma unroll
        for (int i = 0; i < 4; i++)
            #pragma unroll
            for (int j = 0; j < 4; j++)
                red[(4 * tg + i) * 17 + og * 4 + j] = unpack2(acc[i][j]);
    }
    __syncthreads();

    // ---------------- per-token epilogue (32 threads) ----------------
    if (tid < TOKBLK) {
        const int t = tb + tid;
        float nz[16];
        {
            float4 ev[4];
            const float4* ep = reinterpret_cast<const float4*>(eps + (size_t)t * 16);
            ev[0] = ep[0]; ev[1] = ep[1]; ev[2] = ep[2]; ev[3] = ep[3];
            const float* ef = reinterpret_cast<const float*>(ev);
            #pragma unroll
            for (int e = 0; e < 16; e++) {
                float2 l = red[tid * 17 + e];
                nz[e] = l.x + ef[e] * softplus_f(l.y);
            }
        }

        float m = nz[0];
        #pragma unroll
        for (int e = 1; e < 16; e++) m = fmaxf(m, nz[e]);
        float ex[16], ssum = 0.f;
        #pragma unroll
        for (int e = 0; e < 16; e++) { ex[e] = expf(nz[e] - m); ssum += ex[e]; }
        float inv = 1.f / ssum;

        int i1 = 0; float v1 = nz[0];
        #pragma unroll
        for (int e = 1; e < 16; e++) if (nz[e] > v1) { v1 = nz[e]; i1 = e; }
        int i2 = -1; float v2 = -INFINITY;
        #pragma unroll
        for (int e = 0; e < 16; e++) if (e != i1 && nz[e] > v2) { v2 = nz[e]; i2 = e; }

        float t2 = expf(v2 - v1);
        float r1 = 1.f / (1.f + t2);
        float r2 = t2 * r1;

        {
            float ro[16];
            #pragma unroll
            for (int e = 0; e < 16; e++)
                ro[e] = (e == i1) ? r1 : ((e == i2) ? r2 : 0.f);
            float4* op = reinterpret_cast<float4*>(out + (size_t)t * 16);
            op[0] = make_float4(ro[0],  ro[1],  ro[2],  ro[3]);
            op[1] = make_float4(ro[4],  ro[5],  ro[6],  ro[7]);
            op[2] = make_float4(ro[8],  ro[9],  ro[10], ro[11]);
            op[3] = make_float4(ro[12], ro[13], ro[14], ro[15]);
        }
        if (out_size >= IDX_OFF + NTOK * 2) {
            float2* ip = reinterpret_cast<float2*>(out + IDX_OFF + (size_t)t * 2);
            ip[0] = make_float2((float)i1, (float)i2);
        }
        if (out_size >= G1_OFF + NTOK * NEXP) {
            float g[16];
            #pragma unroll
            for (int e = 0; e < 16; e++) g[e] = ex[e] * inv;
            float4* gp = reinterpret_cast<float4*>(out + G1_OFF + (size_t)t * 16);
            gp[0] = make_float4(g[0],  g[1],  g[2],  g[3]);
            gp[1] = make_float4(g[4],  g[5],  g[6],  g[7]);
            gp[2] = make_float4(g[8],  g[9],  g[10], g[11]);
            gp[3] = make_float4(g[12], g[13], g[14], g[15]);
        }
    }
}

// ---------------- launch ----------------
extern "C" void kernel_launch(void* const* d_in, const int* in_sizes, int n_in,
                              void* d_out, int out_size)
{
    const float* mh      = (const float*)d_in[0];
    const float* dt      = (const float*)d_in[1];
    const float* dd      = (const float*)d_in[2];
    const float* drg     = (const float*)d_in[3];
    const float* dent    = (const float*)d_in[4];
    const float* city    = (const float*)d_in[5];
    const float* w_route = (const float*)d_in[6];
    const float* b_route = (const float*)d_in[7];
    const float* w_noise = (const float*)d_in[8];
    const float* b_noise = (const float*)d_in[9];
    const float* eps     = (const float*)d_in[10];
    const int*   ci      = (const int*)d_in[11];

    prep_kernel<<<(LINP * NEXP + 255) / 256, 256>>>(w_route, b_route,
                                                    w_noise, b_noise, city, ci);
    router_main<<<NBLK, TPB>>>(mh, dt, dd, drg, dent, eps,
                               (float*)d_out, out_size);
}

// round 7
// speedup vs baseline: 2.5511x; 2.5511x over previous
#include <cuda_runtime.h>
#include <cstdint>
#include <math.h>

// ---------------- problem constants ----------------
#define NTOK    32768
#define NEXP    16
#define LINP    1792
#define KC      32
#define NCHUNK  56
#define TPB     128
#define TOKBLK  128
#define NBLK    (NTOK / TOKBLK)   // 256

#define IDX_OFF (NTOK * NEXP)
#define G1_OFF  (IDX_OFF + NTOK * 2)

__device__ __align__(16) float2 g_wpack[LINP * NEXP];
__device__ float2 g_bias[NEXP];

// ---------------- helpers ----------------
__device__ __forceinline__ void fma2(unsigned long long& acc,
                                     unsigned long long x,
                                     unsigned long long w) {
    asm("fma.rn.f32x2 %0, %1, %2, %0;" : "+l"(acc) : "l"(x), "l"(w));
}
__device__ __forceinline__ unsigned long long pack2(float v) {
    unsigned long long r;
    asm("mov.b64 %0, {%1, %1};" : "=l"(r) : "f"(v));
    return r;
}
__device__ __forceinline__ unsigned long long packf2(float2 v) {
    unsigned long long r;
    asm("mov.b64 %0, {%1, %2};" : "=l"(r) : "f"(v.x), "f"(v.y));
    return r;
}
__device__ __forceinline__ float2 unpack2(unsigned long long a) {
    float2 r;
    asm("mov.b64 {%0, %1}, %2;" : "=f"(r.x), "=f"(r.y) : "l"(a));
    return r;
}
__device__ __forceinline__ float softplus_f(float x) {
    return fmaxf(x, 0.f) + log1pf(expf(-fabsf(x)));
}
__device__ __forceinline__ uint32_t s2u(const void* p) {
    uint32_t a;
    asm("{ .reg .u64 t; cvta.to.shared.u64 t, %1; cvt.u32.u64 %0, t; }"
        : "=r"(a) : "l"(p));
    return a;
}
__device__ __forceinline__ void cpa16(uint32_t d, const void* s) {
    asm volatile("cp.async.cg.shared.global [%0], [%1], 16;" :: "r"(d), "l"(s));
}
#define CP_COMMIT() asm volatile("cp.async.commit_group;" ::: "memory")
#define CP_WAIT1()  asm volatile("cp.async.wait_group 1;" ::: "memory")
#define CP_WAIT0()  asm volatile("cp.async.wait_group 0;" ::: "memory")

// ---------------- prep ----------------
__global__ void prep_kernel(const float* __restrict__ w_route,
                            const float* __restrict__ b_route,
                            const float* __restrict__ w_noise,
                            const float* __restrict__ b_noise,
                            const float* __restrict__ city_emb,
                            const int*   __restrict__ city_index)
{
    int idx = blockIdx.x * blockDim.x + threadIdx.x;
    if (idx < LINP * NEXP) {
        int pf = idx >> 4, e = idx & 15;
        int g = pf + (pf >= 1024 ? 32 : 0);   // skip city rows [1024,1056)
        g_wpack[idx] = make_float2(w_route[g * 16 + e], w_noise[g * 16 + e]);
    }
    if (idx < NEXP) {
        int ci = city_index[0];
        float br = b_route[idx], bn = b_noise[idx];
        #pragma unroll
        for (int j = 0; j < 32; j++) {
            float cv = city_emb[ci * 32 + j];
            br = fmaf(cv, w_route[(1024 + j) * 16 + idx], br);
            bn = fmaf(cv, w_noise[(1024 + j) * 16 + idx], bn);
        }
        g_bias[idx] = make_float2(br, bn);
    }
}

// ---------------- main kernel ----------------
__global__ __launch_bounds__(TPB, 2)
void router_main(const float* __restrict__ mh,
                 const float* __restrict__ dt,
                 const float* __restrict__ dd,
                 const float* __restrict__ drg,
                 const float* __restrict__ dent,
                 const float* __restrict__ eps,
                 float* __restrict__ out,
                 int out_size)
{
    // main: Xs[2][32][128] floats (32KB) + Wd[2][512] ull (8KB)
    // reduction overlay: parts (3 x 16KB) on whole sm; red [128][17] float2
    __shared__ __align__(16) float sm[12288];   // 48KB
    float* Xs = sm;
    unsigned long long* Wd = reinterpret_cast<unsigned long long*>(sm + 8192);

    const int tid  = threadIdx.x;
    const int lane = tid & 31;
    const int w    = tid >> 5;        // K-quarter
    const int tb   = blockIdx.x * TOKBLK;

    // acc[token i][expert e] = (route, noise) packed f32x2; tokens 4*lane+i
    unsigned long long acc[4][16];
    #pragma unroll
    for (int e = 0; e < 16; e++) {
        unsigned long long b = (w == 0)
            ? *reinterpret_cast<const unsigned long long*>(&g_bias[e])
            : 0ull;
        #pragma unroll
        for (int i = 0; i < 4; i++) acc[i][e] = b;
    }

    // loader: lf = feature quad (0..7), lt = token base (0..15), 8 rounds
    const int lf = tid & 7;
    const int lt = tid >> 3;

    float4 xr[8];

    auto prefetchX = [&](int c) {
        const float* src; int col, stride;
        if (c < 32)      { src = mh;   col = c * 32;        stride = 1024; }
        else if (c < 40) { src = dt;   col = (c - 32) * 32; stride = 256;  }
        else if (c < 48) { src = dd;   col = (c - 40) * 32; stride = 256;  }
        else if (c < 52) { src = drg;  col = (c - 48) * 32; stride = 128;  }
        else             { src = dent; col = (c - 52) * 32; stride = 128;  }
        const float* g = src + (size_t)(tb + lt) * stride + col + 4 * lf;
        #pragma unroll
        for (int q = 0; q < 8; q++)
            xr[q] = *reinterpret_cast<const float4*>(g + (size_t)(16 * q) * stride);
    };
    auto storeX = [&](int b) {
        float* xb = Xs + b * 4096;
        #pragma unroll
        for (int q = 0; q < 8; q++) {
            const int t0 = lt + 16 * q;
            const float* v = reinterpret_cast<const float*>(&xr[q]);
            #pragma unroll
            for (int j = 0; j < 4; j++)
                xb[(4 * lf + j) * 128 + (t0 ^ (4 * lf))] = v[j];
        }
    };
    auto issueW = [&](int c, int b) {
        const char* gw = (const char*)g_wpack + (size_t)c * 4096;
        const uint32_t d = s2u(Wd) + (uint32_t)b * 4096 + tid * 32;
        cpa16(d,      gw + tid * 32);
        cpa16(d + 16, gw + tid * 32 + 16);
    };

    issueW(0, 0); CP_COMMIT();
    prefetchX(0);

    for (int c = 0; c < NCHUNK; c++) {
        const int b = c & 1;
        __syncthreads();                 // (A) compute(c-1) done block-wide
        storeX(b);
        if (c + 1 < NCHUNK) {
            prefetchX(c + 1);
            issueW(c + 1, b ^ 1); CP_COMMIT();
            CP_WAIT1();                  // W(c) landed (this thread's copies)
        } else {
            CP_WAIT0();
        }
        __syncthreads();                 // (B) stores + all W(c) visible

        const float* xb = Xs + b * 4096;
        const unsigned long long* wb = Wd + b * 512;
        #pragma unroll
        for (int k = 0; k < 8; k++) {
            const int f = w * 8 + k;
            const float4 xv = *reinterpret_cast<const float4*>(
                &xb[f * 128 + ((4 * lane) ^ (4 * ((f >> 2) & 7)))]);
            // warp-uniform W for all 16 experts: 8 x LDS.128
            unsigned long long wreg[16];
            const unsigned long long* wf = wb + f * 16;
            #pragma unroll
            for (int e = 0; e < 16; e += 2) {
                ulonglong2 t = *reinterpret_cast<const ulonglong2*>(wf + e);
                wreg[e] = t.x; wreg[e + 1] = t.y;
            }
            const unsigned long long x0 = pack2(xv.x);
            const unsigned long long x1 = pack2(xv.y);
            const unsigned long long x2 = pack2(xv.z);
            const unsigned long long x3 = pack2(xv.w);
            #pragma unroll
            for (int e = 0; e < 16; e++) {
                fma2(acc[0][e], x0, wreg[e]);
                fma2(acc[1][e], x1, wreg[e]);
                fma2(acc[2][e], x2, wreg[e]);
                fma2(acc[3][e], x3, wreg[e]);
            }
        }
    }

    // ---------------- K-split(4) reduction ----------------
    __syncthreads();
    if (w > 0) {
        // partial for warp w at sm + (w-1)*4096 floats, [128][16] float2,
        // column-swizzled: pos = e ^ (lane&15)  (t>>2 == lane for t=4*lane+i)
        float2* P = reinterpret_cast<float2*>(sm + (w - 1) * 4096);
        #pragma unroll
        for (int i = 0; i < 4; i++) {
            const int t = 4 * lane + i;
            #pragma unroll
            for (int e = 0; e < 16; e++)
                P[t * 16 + (e ^ (lane & 15))] = unpack2(acc[i][e]);
        }
    }
    __syncthreads();
    if (w == 0) {
        #pragma unroll
        for (int p = 0; p < 3; p++) {
            const float2* P = reinterpret_cast<const float2*>(sm + p * 4096);
            #pragma unroll
            for (int i = 0; i < 4; i++) {
                const int t = 4 * lane + i;
                #pragma unroll
                for (int e = 0; e < 16; e++) {
                    float2 r = P[t * 16 + (e ^ (lane & 15))];
                    float2 a = unpack2(acc[i][e]);
                    a.x += r.x; a.y += r.y;
                    acc[i][e] = packf2(a);
                }
            }
        }
        __syncwarp();   // all lanes done reading parts before red overwrites
        float2* red = reinterpret_cast<float2*>(sm);   // [128][17]
        #pragma unroll
        for (int i = 0; i < 4; i++) {
            const int t = 4 * lane + i;
            #pragma unroll
            for (int e = 0; e < 16; e++)
                red[t * 17 + e] = unpack2(acc[i][e]);
        }
    }
    __syncthreads();

    // ---------------- per-token epilogue (128 threads, 1 token each) ----------------
    {
        const float2* red = reinterpret_cast<const float2*>(sm);
        const int t = tb + tid;
        float nz[16];
        {
            float4 ev[4];
            const float4* ep = reinterpret_cast<const float4*>(eps + (size_t)t * 16);
            ev[0] = ep[0]; ev[1] = ep[1]; ev[2] = ep[2]; ev[3] = ep[3];
            const float* ef = reinterpret_cast<const float*>(ev);
            #pragma unroll
            for (int e = 0; e < 16; e++) {
                float2 l = red[tid * 17 + e];
                nz[e] = l.x + ef[e] * softplus_f(l.y);
            }
        }

        float m = nz[0];
        #pragma unroll
        for (int e = 1; e < 16; e++) m = fmaxf(m, nz[e]);
        float ex[16], ssum = 0.f;
        #pragma unroll
        for (int e = 0; e < 16; e++) { ex[e] = expf(nz[e] - m); ssum += ex[e]; }
        float inv = 1.f / ssum;

        int i1 = 0; float v1 = nz[0];
        #pragma unroll
        for (int e = 1; e < 16; e++) if (nz[e] > v1) { v1 = nz[e]; i1 = e; }
        int i2 = -1; float v2 = -INFINITY;
        #pragma unroll
        for (int e = 0; e < 16; e++) if (e != i1 && nz[e] > v2) { v2 = nz[e]; i2 = e; }

        float t2 = expf(v2 - v1);
        float r1 = 1.f / (1.f + t2);
        float r2 = t2 * r1;

        {
            float ro[16];
            #pragma unroll
            for (int e = 0; e < 16; e++)
                ro[e] = (e == i1) ? r1 : ((e == i2) ? r2 : 0.f);
            float4* op = reinterpret_cast<float4*>(out + (size_t)t * 16);
            op[0] = make_float4(ro[0],  ro[1],  ro[2],  ro[3]);
            op[1] = make_float4(ro[4],  ro[5],  ro[6],  ro[7]);
            op[2] = make_float4(ro[8],  ro[9],  ro[10], ro[11]);
            op[3] = make_float4(ro[12], ro[13], ro[14], ro[15]);
        }
        if (out_size >= IDX_OFF + NTOK * 2) {
            float2* ip = reinterpret_cast<float2*>(out + IDX_OFF + (size_t)t * 2);
            ip[0] = make_float2((float)i1, (float)i2);
        }
        if (out_size >= G1_OFF + NTOK * NEXP) {
            float g[16];
            #pragma unroll
            for (int e = 0; e < 16; e++) g[e] = ex[e] * inv;
            float4* gp = reinterpret_cast<float4*>(out + G1_OFF + (size_t)t * 16);
            gp[0] = make_float4(g[0],  g[1],  g[2],  g[3]);
            gp[1] = make_float4(g[4],  g[5],  g[6],  g[7]);
            gp[2] = make_float4(g[8],  g[9],  g[10], g[11]);
            gp[3] = make_float4(g[12], g[13], g[14], g[15]);
        }
    }
}

// ---------------- launch ----------------
extern "C" void kernel_launch(void* const* d_in, const int* in_sizes, int n_in,
                              void* d_out, int out_size)
{
    const float* mh      = (const float*)d_in[0];
    const float* dt      = (const float*)d_in[1];
    const float* dd      = (const float*)d_in[2];
    const float* drg     = (const float*)d_in[3];
    const float* dent    = (const float*)d_in[4];
    const float* city    = (const float*)d_in[5];
    const float* w_route = (const float*)d_in[6];
    const float* b_route = (const float*)d_in[7];
    const float* w_noise = (const float*)d_in[8];
    const float* b_noise = (const float*)d_in[9];
    const float* eps     = (const float*)d_in[10];
    const int*   ci      = (const int*)d_in[11];

    prep_kernel<<<(LINP * NEXP + 255) / 256, 256>>>(w_route, b_route,
                                                    w_noise, b_noise, city, ci);
    router_main<<<NBLK, TPB>>>(mh, dt, dd, drg, dent, eps,
                               (float*)d_out, out_size);
}